// round 6
// baseline (speedup 1.0000x reference)
#include <cuda_runtime.h>
#include <cuda_bf16.h>
#include <cstdint>

// NanEuclidean: X[4096,1024] f32, Y[4096,1024] f32 (10% NaN) -> out[4096,4096] f32
//   d = sqrt( clip(XX.pY - 2 Xc.Yc + pX.YY, 0) / max(1, pX.pY) * 1024 ), NaN where pc==0
//
// Portable tensor-core path (target is plain sm_103 -> no tcgen05):
//   prep: bf16 component planes, pre-swizzled SW128 tile images in device scratch
//   gemm: cp.async 2-stage pipeline + ldmatrix + mma.sync m16n8k16 bf16,
//         two f32 accumulators (D and presence-count), fused epilogue.

#define DDIM  1024
#define NKB   16            // K chunks of 64
#define TILEB 16384u        // one 128-row x 128-byte swizzled tile image
#define STAGEB (6u * TILEB) // A0 A1 A2 B0 B1 B2 = 96 KB
#define GSMEM  (2u * STAGEB + 1024u)

// 24 MB each: [row_block(32)][comp(3)][k_block(16)] 16KB swizzled tiles
__device__ __align__(1024) __nv_bfloat16 g_nanEuc_A[12582912ull];
__device__ __align__(1024) __nv_bfloat16 g_nanEuc_B[12582912ull];

// ---------------- helpers ----------------
__device__ __forceinline__ uint32_t smem_u32(const void* p) {
    uint32_t a;
    asm("{ .reg .u64 t; cvta.to.shared.u64 t, %1; cvt.u32.u64 %0, t; }" : "=r"(a) : "l"(p));
    return a;
}

__device__ __forceinline__ void cpasync16(uint32_t dst, const void* src) {
    asm volatile("cp.async.cg.shared.global [%0], [%1], 16;" :: "r"(dst), "l"(src) : "memory");
}

#define LDSM4(r0, r1, r2, r3, addr) \
    asm volatile("ldmatrix.sync.aligned.m8n8.x4.shared.b16 {%0,%1,%2,%3}, [%4];" \
        : "=r"(r0), "=r"(r1), "=r"(r2), "=r"(r3) : "r"(addr))

__device__ __forceinline__ void mma16816(float* c, const uint32_t* a, const uint32_t* b) {
    asm volatile(
        "mma.sync.aligned.m16n8k16.row.col.f32.bf16.bf16.f32 "
        "{%0,%1,%2,%3}, {%4,%5,%6,%7}, {%8,%9}, {%0,%1,%2,%3};"
        : "+f"(c[0]), "+f"(c[1]), "+f"(c[2]), "+f"(c[3])
        : "r"(a[0]), "r"(a[1]), "r"(a[2]), "r"(a[3]), "r"(b[0]), "r"(b[1]));
}

__device__ __forceinline__ bool nan_bits(float x) {
    return (__float_as_uint(x) & 0x7fffffffu) > 0x7f800000u;  // fast-math safe
}

// ---------------- Kernel 1: precompute swizzled bf16 component tiles ----------------
// A comps (from X): [XX, Xc, pX].  B comps (from Y): [pY, -2*Yc, YY].
__global__ void __launch_bounds__(256) nanEuc_prep(const float* __restrict__ src, int is_b) {
    unsigned idx  = blockIdx.x * 256u + threadIdx.x;   // 4096 rows * 512 k-pairs
    unsigned lane = idx & 31u;            // k-pair within 64-wide k block
    unsigned kb   = (idx >> 5) & 15u;     // k block
    unsigned row  = idx >> 9;             // 0..4095
    const float2 v = *reinterpret_cast<const float2*>(src + (size_t)row * DDIM + kb * 64u + lane * 2u);
    bool  m0 = nan_bits(v.x), m1 = nan_bits(v.y);
    float a0 = m0 ? 0.f : v.x, a1 = m1 ? 0.f : v.y;
    float p0 = m0 ? 0.f : 1.f, p1 = m1 ? 0.f : 1.f;
    float c00, c01, c10, c11, c20, c21;
    if (!is_b) { c00 = a0 * a0; c01 = a1 * a1; c10 = a0;        c11 = a1;        c20 = p0;      c21 = p1; }
    else       { c00 = p0;      c01 = p1;      c10 = -2.f * a0; c11 = -2.f * a1; c20 = a0 * a0; c21 = a1 * a1; }
    unsigned rb = row >> 7, r = row & 127u;
    unsigned off = r * 128u + lane * 4u;          // byte offset inside 128x128B tile
    unsigned sw  = off ^ ((off >> 3) & 0x70u);    // SW128
    char* dst = reinterpret_cast<char*>(is_b ? g_nanEuc_B : g_nanEuc_A);
    size_t base = ((size_t)rb * 48u + kb) * 16384u;       // comp stride = 16*16384
    *reinterpret_cast<__nv_bfloat162*>(dst + base +           sw) = __floats2bfloat162_rn(c00, c01);
    *reinterpret_cast<__nv_bfloat162*>(dst + base + 262144u + sw) = __floats2bfloat162_rn(c10, c11);
    *reinterpret_cast<__nv_bfloat162*>(dst + base + 524288u + sw) = __floats2bfloat162_rn(c20, c21);
}

// ---------------- Kernel 2: mma.sync GEMM with dual accumulators ----------------
// 512 threads = 16 warps in 4x4; warp tile 32x32; CTA tile 128x128.
__global__ void __launch_bounds__(512) nanEuc_gemm(float* __restrict__ out) {
    extern __shared__ char smraw[];
    const uint32_t smbase = (smem_u32(smraw) + 1023u) & ~1023u;

    const int tid = threadIdx.x, lane = tid & 31, w = tid >> 5;
    const int wr = w >> 2, wc = w & 3;
    const int cb = blockIdx.x, rb = blockIdx.y;

    const char* Ag = reinterpret_cast<const char*>(g_nanEuc_A);
    const char* Bg = reinterpret_cast<const char*>(g_nanEuc_B);

    float accD[2][4][4];
    float accP[2][4][4];
    #pragma unroll
    for (int mi = 0; mi < 2; mi++)
        #pragma unroll
        for (int ni = 0; ni < 4; ni++)
            #pragma unroll
            for (int q = 0; q < 4; q++) { accD[mi][ni][q] = 0.f; accP[mi][ni][q] = 0.f; }

    // ldmatrix lane address components.
    // A (m16k16, x4): row = mbase + (lane&15), 16B-seg = lane>>4
    // B (n16k16, x4): row = nbase + (lane&7) + ((lane>>4)&1)*8, 16B-seg = (lane>>3)&1
    const uint32_t segA = (uint32_t)(lane >> 4) * 16u;
    const uint32_t segB = (uint32_t)((lane >> 3) & 1) * 16u;
    uint32_t rtermA[2], xorA[2], rtermB[2], xorB[2];
    #pragma unroll
    for (int mi = 0; mi < 2; mi++) {
        uint32_t rowA = wr * 32 + mi * 16 + (lane & 15);
        rtermA[mi] = rowA * 128u;  xorA[mi] = (rowA & 7u) * 16u;
    }
    #pragma unroll
    for (int nt = 0; nt < 2; nt++) {
        uint32_t rowB = wc * 32 + nt * 16 + (lane & 7) + ((lane >> 4) & 1) * 8;
        rtermB[nt] = rowB * 128u;  xorB[nt] = (rowB & 7u) * 16u;
    }

    // stage loader: 6 contiguous 16KB tiles; i-th 16B chunk: tile = i>>10
    auto load_stage = [&](int s, int c) {
        const uint32_t dst0 = smbase + (uint32_t)s * STAGEB;
        #pragma unroll
        for (int i = tid; i < (int)(STAGEB / 16u); i += 512) {
            int t = i >> 10;                 // 0..5
            int comp = (t < 3) ? t : t - 3;
            const char* src = (t < 3
                ? Ag + ((size_t)(rb * 3 + comp) * NKB + c) * TILEB
                : Bg + ((size_t)(cb * 3 + comp) * NKB + c) * TILEB)
                + (size_t)(i & 1023) * 16u;
            cpasync16(dst0 + (uint32_t)i * 16u, src);
        }
        asm volatile("cp.async.commit_group;" ::: "memory");
    };

    load_stage(0, 0);
    load_stage(1, 1);

    for (int c = 0; c < NKB; c++) {
        const int s = c & 1;
        if (c + 1 < NKB) asm volatile("cp.async.wait_group 1;" ::: "memory");
        else             asm volatile("cp.async.wait_group 0;" ::: "memory");
        __syncthreads();

        const uint32_t base = smbase + (uint32_t)s * STAGEB;
        #pragma unroll
        for (int kk = 0; kk < 4; kk++) {
            const uint32_t kbA = (uint32_t)kk * 32u + segA;
            const uint32_t kbB = (uint32_t)kk * 32u + segB;
            uint32_t a[2][4], b[4][2], bP[4][2];

            // ---- comp 0: D += XX . pY^T ; save pY frags for PC ----
            #pragma unroll
            for (int mi = 0; mi < 2; mi++)
                LDSM4(a[mi][0], a[mi][1], a[mi][2], a[mi][3],
                      base + 0u * TILEB + rtermA[mi] + (kbA ^ xorA[mi]));
            #pragma unroll
            for (int nt = 0; nt < 2; nt++)
                LDSM4(b[2 * nt][0], b[2 * nt][1], b[2 * nt + 1][0], b[2 * nt + 1][1],
                      base + 3u * TILEB + rtermB[nt] + (kbB ^ xorB[nt]));
            #pragma unroll
            for (int ni = 0; ni < 4; ni++) { bP[ni][0] = b[ni][0]; bP[ni][1] = b[ni][1]; }
            #pragma unroll
            for (int mi = 0; mi < 2; mi++)
                #pragma unroll
                for (int ni = 0; ni < 4; ni++) mma16816(accD[mi][ni], a[mi], b[ni]);

            // ---- comp 1: D += Xc . (-2 Yc)^T ----
            #pragma unroll
            for (int mi = 0; mi < 2; mi++)
                LDSM4(a[mi][0], a[mi][1], a[mi][2], a[mi][3],
                      base + 1u * TILEB + rtermA[mi] + (kbA ^ xorA[mi]));
            #pragma unroll
            for (int nt = 0; nt < 2; nt++)
                LDSM4(b[2 * nt][0], b[2 * nt][1], b[2 * nt + 1][0], b[2 * nt + 1][1],
                      base + 4u * TILEB + rtermB[nt] + (kbB ^ xorB[nt]));
            #pragma unroll
            for (int mi = 0; mi < 2; mi++)
                #pragma unroll
                for (int ni = 0; ni < 4; ni++) mma16816(accD[mi][ni], a[mi], b[ni]);

            // ---- comp 2: D += pX . YY^T ; PC += pX . pY^T ----
            #pragma unroll
            for (int mi = 0; mi < 2; mi++)
                LDSM4(a[mi][0], a[mi][1], a[mi][2], a[mi][3],
                      base + 2u * TILEB + rtermA[mi] + (kbA ^ xorA[mi]));
            #pragma unroll
            for (int nt = 0; nt < 2; nt++)
                LDSM4(b[2 * nt][0], b[2 * nt][1], b[2 * nt + 1][0], b[2 * nt + 1][1],
                      base + 5u * TILEB + rtermB[nt] + (kbB ^ xorB[nt]));
            #pragma unroll
            for (int mi = 0; mi < 2; mi++)
                #pragma unroll
                for (int ni = 0; ni < 4; ni++) {
                    mma16816(accD[mi][ni], a[mi], b[ni]);
                    mma16816(accP[mi][ni], a[mi], bP[ni]);
                }
        }
        __syncthreads();
        if (c + 2 < NKB) load_stage(s, c + 2);
    }

    // ---- epilogue: r = pc==0 ? NaN : sqrt(max(d,0) * 1024 / max(pc,1)) ----
    const int r0 = rb * 128 + wr * 32 + (lane >> 2);
    const int c0 = cb * 128 + wc * 32 + (lane & 3) * 2;
    #pragma unroll
    for (int mi = 0; mi < 2; mi++)
        #pragma unroll
        for (int ni = 0; ni < 4; ni++) {
            const int rr = r0 + mi * 16;
            const int cc = c0 + ni * 8;
            float v[4];
            #pragma unroll
            for (int q = 0; q < 4; q++) {
                float d = accD[mi][ni][q], p = accP[mi][ni][q];
                v[q] = (p == 0.f) ? __int_as_float(0x7fc00000)
                                  : sqrtf(fmaxf(d, 0.f) * 1024.f / fmaxf(p, 1.f));
            }
            *reinterpret_cast<float2*>(out + (size_t)rr * 4096u + cc)       = make_float2(v[0], v[1]);
            *reinterpret_cast<float2*>(out + (size_t)(rr + 8) * 4096u + cc) = make_float2(v[2], v[3]);
        }
}

// ---------------- launch ----------------
extern "C" void kernel_launch(void* const* d_in, const int* in_sizes, int n_in,
                              void* d_out, int out_size) {
    (void)in_sizes; (void)n_in; (void)out_size;
    const float* X = (const float*)d_in[0];
    const float* Y = (const float*)d_in[1];
    float* out = (float*)d_out;

    nanEuc_prep<<<8192, 256>>>(X, 0);
    nanEuc_prep<<<8192, 256>>>(Y, 1);

    cudaFuncSetAttribute(nanEuc_gemm, cudaFuncAttributeMaxDynamicSharedMemorySize, GSMEM);
    nanEuc_gemm<<<dim3(32, 32, 1), 512, GSMEM>>>(out);
}